// round 3
// baseline (speedup 1.0000x reference)
#include <cuda_runtime.h>
#include <math.h>

#define NN 10000
#define CC 128
#define DD 20
#define KK 16
#define NK (NN*KK)
#define SPLIT 16
#define SPLIT_LEN (NN/SPLIT)      // 625
#define BN_EPS 1e-5f
#define F_INF __int_as_float(0x7f800000)

// ---------------- scratch (static device globals; no allocation) ----------------
__device__ float g_h[NN*DD];           // pre-BN activations
__device__ float g_emb[NN*DD];         // post-BN/ReLU embedding (pre-noise, for KNN)
__device__ float g_embn[NN*DD];        // emb + noise*1e-4 (for p)
__device__ float g_sqe[NN];            // ||emb_i||^2  (reference summation order)
__device__ float g_sqp[NN];            // ||pos_i||^2  (reference summation order)
__device__ float g_mu[DD];
__device__ float g_var[DD];
__device__ float g_pd[SPLIT*NN*KK];    // partial top-k distances per split
__device__ int   g_pi[SPLIT*NN*KK];    // partial top-k indices per split
__device__ int   g_knn_e[NK];          // final emb-knn indices
__device__ int   g_knn_p[NK];          // final pos-knn indices

// ---------------- 1. MLP: h = x@W + b  (ascending-k FMA chain, cuBLAS order) ----------------
__global__ void mlp_kernel(const float* __restrict__ x,
                           const float* __restrict__ W,
                           const float* __restrict__ b) {
    __shared__ float sW[CC*DD];
    for (int i = threadIdx.x; i < CC*DD; i += blockDim.x) sW[i] = W[i];
    __syncthreads();
    int n = blockIdx.x * blockDim.x + threadIdx.x;
    if (n >= NN) return;
    float acc[DD];
    #pragma unroll
    for (int d = 0; d < DD; ++d) acc[d] = 0.f;
    const float4* xr = reinterpret_cast<const float4*>(x + n * CC);
    #pragma unroll 4
    for (int c4 = 0; c4 < CC/4; ++c4) {
        float4 xv = xr[c4];
        #pragma unroll
        for (int d = 0; d < DD; ++d) {
            // ascending k within each output: sequential fma chain
            acc[d] = fmaf(xv.x, sW[(4*c4+0)*DD + d], acc[d]);
            acc[d] = fmaf(xv.y, sW[(4*c4+1)*DD + d], acc[d]);
            acc[d] = fmaf(xv.z, sW[(4*c4+2)*DD + d], acc[d]);
            acc[d] = fmaf(xv.w, sW[(4*c4+3)*DD + d], acc[d]);
        }
    }
    #pragma unroll
    for (int d = 0; d < DD; ++d) g_h[n*DD + d] = __fadd_rn(acc[d], b[d]);
}

// ---------------- 2. BN stats ----------------
__global__ void bn_stats_kernel() {
    __shared__ float s1[256], s2[256];
    int c = blockIdx.x;
    float a = 0.f, bb = 0.f;
    for (int n = threadIdx.x; n < NN; n += 256) {
        float v = g_h[n*DD + c];
        a += v;
        bb = fmaf(v, v, bb);
    }
    s1[threadIdx.x] = a; s2[threadIdx.x] = bb;
    __syncthreads();
    for (int st = 128; st > 0; st >>= 1) {
        if (threadIdx.x < st) {
            s1[threadIdx.x] += s1[threadIdx.x + st];
            s2[threadIdx.x] += s2[threadIdx.x + st];
        }
        __syncthreads();
    }
    if (threadIdx.x == 0) {
        float m = s1[0] / (float)NN;
        g_mu[c]  = m;
        g_var[c] = s2[0] / (float)NN - m * m;
    }
}

// ---------------- 3. BN apply + ReLU + noise + sq-norms ----------------
// sq uses the reference order: individually-rounded products, sequential
// ascending adds (no fma contraction -> forced intrinsics).
__global__ void bn_apply_kernel(const float* __restrict__ noise,
                                const float* __restrict__ gamma,
                                const float* __restrict__ beta) {
    int n = blockIdx.x * blockDim.x + threadIdx.x;
    if (n >= NN) return;
    float v0[DD];
    #pragma unroll
    for (int d = 0; d < DD; ++d) {
        float v = __fmul_rn(__fmul_rn(__fsub_rn(g_h[n*DD + d], g_mu[d]),
                                      rsqrtf(__fadd_rn(g_var[d], BN_EPS))),
                            gamma[d]);
        v = __fadd_rn(v, beta[d]);
        v = fmaxf(v, 0.f);
        v0[d] = v;
        g_emb[n*DD + d]  = v;
        g_embn[n*DD + d] = __fadd_rn(v, __fmul_rn(noise[n*DD + d], 1e-4f));
    }
    float sq = __fmul_rn(v0[0], v0[0]);
    #pragma unroll
    for (int d = 1; d < DD; ++d) sq = __fadd_rn(sq, __fmul_rn(v0[d], v0[d]));
    g_sqe[n] = sq;
}

__global__ void possq_kernel(const float* __restrict__ pos) {
    int n = blockIdx.x * blockDim.x + threadIdx.x;
    if (n >= NN) return;
    float a = pos[n*3 + 0], b = pos[n*3 + 1], c = pos[n*3 + 2];
    float sq = __fmul_rn(a, a);
    sq = __fadd_rn(sq, __fmul_rn(b, b));
    sq = __fadd_rn(sq, __fmul_rn(c, c));
    g_sqp[n] = sq;
}

// ---------------- 4. brute-force KNN, candidates split SPLIT ways ----------------
// Replicates the reference distance arithmetic:
//   dot  = ascending-k fma chain from 0            (cuBLAS SGEMM order)
//   d2   = (sq_i + sq_j) - 2*dot                   (exact op order)
template<int DIMS, int DPAD, bool EMB>
__global__ void knn_partial_kernel(const float* __restrict__ posfeat) {
    const int TS = 128;
    const float* feat = EMB ? g_emb : posfeat;
    const float* sqn  = EMB ? g_sqe : g_sqp;
    __shared__ __align__(16) float sf[TS * DPAD];
    __shared__ float ssq[TS];

    int q = blockIdx.x * TS + threadIdx.x;
    bool valid = q < NN;
    float qf[DPAD];
    float qsq = 0.f;
    #pragma unroll
    for (int d = 0; d < DPAD; ++d) qf[d] = 0.f;
    if (valid) {
        #pragma unroll
        for (int d = 0; d < DIMS; ++d) qf[d] = feat[q*DIMS + d];
        qsq = sqn[q];
    }
    float bd[KK]; int bi[KK];
    #pragma unroll
    for (int s = 0; s < KK; ++s) { bd[s] = F_INF; bi[s] = 0; }

    int c0 = blockIdx.y * SPLIT_LEN;
    int c1 = c0 + SPLIT_LEN;
    for (int base = c0; base < c1; base += TS) {
        int cnt = min(TS, c1 - base);
        __syncthreads();
        for (int l = threadIdx.x; l < cnt * DIMS; l += TS) {
            int j = l / DIMS;
            sf[j*DPAD + (l - j*DIMS)] = feat[base*DIMS + l];
        }
        if (threadIdx.x < cnt) ssq[threadIdx.x] = sqn[base + threadIdx.x];
        __syncthreads();
        if (!valid) continue;

        #pragma unroll 2
        for (int j = 0; j < cnt; ++j) {
            float dot = 0.f;
            #pragma unroll
            for (int v = 0; v < DPAD/4; ++v) {
                float4 r = *reinterpret_cast<const float4*>(&sf[j*DPAD + 4*v]);
                if (4*v+0 < DIMS) dot = fmaf(qf[4*v+0], r.x, dot);
                if (4*v+1 < DIMS) dot = fmaf(qf[4*v+1], r.y, dot);
                if (4*v+2 < DIMS) dot = fmaf(qf[4*v+2], r.z, dot);
                if (4*v+3 < DIMS) dot = fmaf(qf[4*v+3], r.w, dot);
            }
            float d2 = __fsub_rn(__fadd_rn(qsq, ssq[j]), __fmul_rn(2.f, dot));
            int cj = base + j;
            if (cj != q && d2 < bd[KK-1]) {
                // insertion via compare-swap chain; strict '<' keeps earlier
                // (lower-index) entries ahead on ties, matching jax top_k.
                float cd = d2; int ci = cj;
                #pragma unroll
                for (int s = 0; s < KK; ++s) {
                    bool sw = cd < bd[s];
                    float td = sw ? bd[s] : cd;
                    int   ti = sw ? bi[s] : ci;
                    if (sw) { bd[s] = cd; bi[s] = ci; }
                    cd = td; ci = ti;
                }
            }
        }
    }
    if (valid) {
        int off = (blockIdx.y * NN + q) * KK;
        #pragma unroll
        for (int s = 0; s < KK; ++s) { g_pd[off + s] = bd[s]; g_pi[off + s] = bi[s]; }
    }
}

// Merge SPLIT sorted 16-lists per query via head-scan argmin.
// Lists are ordered by candidate range, so strict '<' (prefer lowest list on
// ties) preserves lower-index-first semantics.
template<bool EMB>
__global__ void knn_merge_kernel() {
    int q = blockIdx.x * blockDim.x + threadIdx.x;
    if (q >= NN) return;
    int* out = EMB ? g_knn_e : g_knn_p;
    float hd[SPLIT];
    int   hp[SPLIT];
    #pragma unroll
    for (int l = 0; l < SPLIT; ++l) {
        hd[l] = g_pd[(l*NN + q) * KK];
        hp[l] = 0;
    }
    for (int s = 0; s < KK; ++s) {
        int best = 0; float bv = hd[0];
        #pragma unroll
        for (int l = 1; l < SPLIT; ++l) {
            if (hd[l] < bv) { bv = hd[l]; best = l; }
        }
        out[q*KK + s] = g_pi[(best*NN + q) * KK + hp[best]];
        hp[best]++;
        hd[best] = (hp[best] < KK) ? g_pd[(best*NN + q) * KK + hp[best]] : F_INF;
    }
}

// ---------------- 5. edge outputs ----------------
// out layout (float32, concatenated reference tuple, row-major):
//  [0,NK) p | [NK,2NK) p | [2NK,3NK) dst | [3NK,4NK) emb src | [4NK,5NK) dst
//  [5NK,6NK) emb src | [6NK,7NK) pos src | [7NK,8NK) dst | [8NK,9NK) dst
__global__ void edge_kernel(const float* __restrict__ t, float* __restrict__ out) {
    int e = blockIdx.x * blockDim.x + threadIdx.x;
    if (e >= NK) return;
    int dst = e >> 4;          // K = 16
    int src = g_knn_e[e];
    const float* a = g_embn + src * DD;
    const float* b = g_embn + dst * DD;
    float s = 0.f;
    #pragma unroll
    for (int d = 0; d < DD; ++d) {
        float df = a[d] - b[d];
        s = fmaf(df, df, s);
    }
    float p = expf(-t[0] * sqrtf(s));
    float fdst = (float)dst;
    out[e]          = p;
    out[NK   + e]   = p;
    out[2*NK + e]   = fdst;
    out[3*NK + e]   = (float)src;
    out[4*NK + e]   = fdst;
    out[5*NK + e]   = (float)src;
    out[6*NK + e]   = (float)g_knn_p[e];
    out[7*NK + e]   = fdst;
    out[8*NK + e]   = fdst;
}

// ---------------- launch ----------------
extern "C" void kernel_launch(void* const* d_in, const int* in_sizes, int n_in,
                              void* d_out, int out_size) {
    const float* x     = (const float*)d_in[0];
    const float* pos   = (const float*)d_in[1];
    const float* noise = (const float*)d_in[2];
    const float* W     = (const float*)d_in[3];
    const float* b     = (const float*)d_in[4];
    const float* gamma = (const float*)d_in[5];
    const float* beta  = (const float*)d_in[6];
    const float* t     = (const float*)d_in[7];
    float* out = (float*)d_out;

    const int TB = 128;
    int nb = (NN + TB - 1) / TB;      // 79

    mlp_kernel<<<nb, TB>>>(x, W, b);
    bn_stats_kernel<<<DD, 256>>>();
    bn_apply_kernel<<<nb, TB>>>(noise, gamma, beta);
    possq_kernel<<<nb, TB>>>(pos);

    dim3 kg(nb, SPLIT);
    knn_partial_kernel<DD, DD, true><<<kg, TB>>>(nullptr);
    knn_merge_kernel<true><<<nb, TB>>>();
    knn_partial_kernel<3, 4, false><<<kg, TB>>>(pos);
    knn_merge_kernel<false><<<nb, TB>>>();

    edge_kernel<<<(NK + 255) / 256, 256>>>(t, out);
}

// round 14
// speedup vs baseline: 1.4878x; 1.4878x over previous
#include <cuda_runtime.h>
#include <math.h>

#define NN 10000
#define CC 128
#define DD 20
#define KK 16
#define NK (NN*KK)
#define SPL 7
#define TS 160
#define NBQ 63          // ceil(10000/160)
#define BUFCAP 16
#define BN_EPS 1e-5f
#define F_INF __int_as_float(0x7f800000)

// ---------------- scratch (static device globals; no allocation) ----------------
__device__ float g_h[NN*DD];           // pre-BN activations
__device__ float g_emb[NN*DD];         // post-BN/ReLU embedding (pre-noise, for KNN)
__device__ float g_embn[NN*DD];        // emb + noise*1e-4 (for p)
__device__ float g_sqe[NN];            // ||emb_i||^2  (reference summation order)
__device__ float g_sqp[NN];            // ||pos_i||^2  (reference summation order)
__device__ float g_mu[DD];
__device__ float g_var[DD];
__device__ float g_pd[SPL*NN*KK];      // partial top-k distances per split
__device__ int   g_pi[SPL*NN*KK];      // partial top-k indices per split
__device__ int   g_knn_e[NK];          // final emb-knn indices
__device__ int   g_knn_p[NK];          // final pos-knn indices

// ---------------- 1. MLP: h = x@W + b  (ascending-k FMA chain) ----------------
__global__ void mlp_kernel(const float* __restrict__ x,
                           const float* __restrict__ W,
                           const float* __restrict__ b) {
    __shared__ float sW[CC*DD];
    for (int i = threadIdx.x; i < CC*DD; i += blockDim.x) sW[i] = W[i];
    __syncthreads();
    int n = blockIdx.x * blockDim.x + threadIdx.x;
    if (n >= NN) return;
    float acc[DD];
    #pragma unroll
    for (int d = 0; d < DD; ++d) acc[d] = 0.f;
    const float4* xr = reinterpret_cast<const float4*>(x + n * CC);
    #pragma unroll 4
    for (int c4 = 0; c4 < CC/4; ++c4) {
        float4 xv = xr[c4];
        #pragma unroll
        for (int d = 0; d < DD; ++d) {
            acc[d] = fmaf(xv.x, sW[(4*c4+0)*DD + d], acc[d]);
            acc[d] = fmaf(xv.y, sW[(4*c4+1)*DD + d], acc[d]);
            acc[d] = fmaf(xv.z, sW[(4*c4+2)*DD + d], acc[d]);
            acc[d] = fmaf(xv.w, sW[(4*c4+3)*DD + d], acc[d]);
        }
    }
    #pragma unroll
    for (int d = 0; d < DD; ++d) g_h[n*DD + d] = __fadd_rn(acc[d], b[d]);
}

// ---------------- 2. BN stats ----------------
__global__ void bn_stats_kernel() {
    __shared__ float s1[256], s2[256];
    int c = blockIdx.x;
    float a = 0.f, bb = 0.f;
    for (int n = threadIdx.x; n < NN; n += 256) {
        float v = g_h[n*DD + c];
        a += v;
        bb = fmaf(v, v, bb);
    }
    s1[threadIdx.x] = a; s2[threadIdx.x] = bb;
    __syncthreads();
    for (int st = 128; st > 0; st >>= 1) {
        if (threadIdx.x < st) {
            s1[threadIdx.x] += s1[threadIdx.x + st];
            s2[threadIdx.x] += s2[threadIdx.x + st];
        }
        __syncthreads();
    }
    if (threadIdx.x == 0) {
        float m = s1[0] / (float)NN;
        g_mu[c]  = m;
        g_var[c] = s2[0] / (float)NN - m * m;
    }
}

// ---------------- 3. BN apply + ReLU + noise + both sq-norms ----------------
__global__ void bn_apply_kernel(const float* __restrict__ noise,
                                const float* __restrict__ gamma,
                                const float* __restrict__ beta,
                                const float* __restrict__ pos) {
    int n = blockIdx.x * blockDim.x + threadIdx.x;
    if (n >= NN) return;
    float v0[DD];
    #pragma unroll
    for (int d = 0; d < DD; ++d) {
        float v = __fmul_rn(__fmul_rn(__fsub_rn(g_h[n*DD + d], g_mu[d]),
                                      rsqrtf(__fadd_rn(g_var[d], BN_EPS))),
                            gamma[d]);
        v = __fadd_rn(v, beta[d]);
        v = fmaxf(v, 0.f);
        v0[d] = v;
        g_emb[n*DD + d]  = v;
        g_embn[n*DD + d] = __fadd_rn(v, __fmul_rn(noise[n*DD + d], 1e-4f));
    }
    float sq = __fmul_rn(v0[0], v0[0]);
    #pragma unroll
    for (int d = 1; d < DD; ++d) sq = __fadd_rn(sq, __fmul_rn(v0[d], v0[d]));
    g_sqe[n] = sq;

    float a = pos[n*3 + 0], b = pos[n*3 + 1], c = pos[n*3 + 2];
    float sp = __fmul_rn(a, a);
    sp = __fadd_rn(sp, __fmul_rn(b, b));
    sp = __fadd_rn(sp, __fmul_rn(c, c));
    g_sqp[n] = sp;
}

// ---------------- 4. brute-force KNN with buffered top-16 insertion ----------------
// d2 arithmetic replicates the reference exactly (ascending-k fma chain from 0,
// then (sq_i + sq_j) - 2*dot). Candidates passing the cached threshold are pushed
// (in ascending order) into a per-lane smem buffer; the 16-stage compare-swap
// network runs only when some lane's buffer fills. Tie-semantics identical to
// immediate insertion (strict '<' keeps earlier = lower indices ahead).
template<int DIMS, int DPAD, bool EMB>
__global__ void knn_kernel(const float* __restrict__ posfeat) {
    const float* feat = EMB ? g_emb : posfeat;
    const float* sqn  = EMB ? g_sqe : g_sqp;
    __shared__ __align__(16) float sf[TS * DPAD];
    __shared__ float ssq[TS];
    __shared__ unsigned long long sbuf[BUFCAP * TS];

    int tid = threadIdx.x;
    int q = blockIdx.x * TS + tid;
    bool valid = q < NN;
    float qf[DIMS];
    float qsq = F_INF;                       // invalid lanes: d2 = inf -> never push
    #pragma unroll
    for (int d = 0; d < DIMS; ++d) qf[d] = 0.f;
    if (valid) {
        #pragma unroll
        for (int d = 0; d < DIMS; ++d) qf[d] = feat[q*DIMS + d];
        qsq = sqn[q];
    }
    float bd[KK]; int bi[KK];
    #pragma unroll
    for (int s = 0; s < KK; ++s) { bd[s] = F_INF; bi[s] = 0; }
    float thr = F_INF;
    int cnt = 0;

    int c0 = (int)(((long long)blockIdx.y     * NN) / SPL);
    int c1 = (int)(((long long)(blockIdx.y+1) * NN) / SPL);

    for (int base = c0; base < c1; base += TS) {
        int tcnt = min(TS, c1 - base);
        __syncthreads();
        for (int l = tid; l < tcnt * DIMS; l += TS) {
            int j = l / DIMS;
            sf[j*DPAD + (l - j*DIMS)] = feat[base*DIMS + l];
        }
        if (tid < tcnt) {
            if (EMB) ssq[tid] = sqn[base + tid];
            else     sf[tid*DPAD + 3] = sqn[base + tid];
        }
        __syncthreads();

        for (int j = 0; j < tcnt; ++j) {
            float dot = 0.f;
            float ssqj;
            if (EMB) {
                #pragma unroll
                for (int v = 0; v < DIMS/4; ++v) {
                    float4 r = *reinterpret_cast<const float4*>(&sf[j*DPAD + 4*v]);
                    dot = fmaf(qf[4*v+0], r.x, dot);
                    dot = fmaf(qf[4*v+1], r.y, dot);
                    dot = fmaf(qf[4*v+2], r.z, dot);
                    dot = fmaf(qf[4*v+3], r.w, dot);
                }
                ssqj = ssq[j];
            } else {
                float4 r = *reinterpret_cast<const float4*>(&sf[j*DPAD]);
                dot = fmaf(qf[0], r.x, dot);
                dot = fmaf(qf[1], r.y, dot);
                dot = fmaf(qf[2], r.z, dot);
                ssqj = r.w;
            }
            float d2 = __fsub_rn(__fadd_rn(qsq, ssqj), __fmul_rn(2.f, dot));
            int cj = base + j;
            if (cj != q && d2 < thr) {
                sbuf[cnt*TS + tid] =
                    ((unsigned long long)__float_as_uint(d2) << 32) | (unsigned)cj;
                cnt++;
            }
            if (__any_sync(0xffffffffu, cnt == BUFCAP)) {
                for (int m = 0; m < cnt; ++m) {
                    unsigned long long pk = sbuf[m*TS + tid];
                    float cd = __uint_as_float((unsigned)(pk >> 32));
                    int ci = (int)(unsigned)pk;
                    if (cd < bd[KK-1]) {
                        #pragma unroll
                        for (int s = 0; s < KK; ++s) {
                            bool sw = cd < bd[s];
                            float td = sw ? bd[s] : cd;
                            int   ti = sw ? bi[s] : ci;
                            if (sw) { bd[s] = cd; bi[s] = ci; }
                            cd = td; ci = ti;
                        }
                    }
                }
                cnt = 0;
                thr = bd[KK-1];
            }
        }
    }
    // final flush
    for (int m = 0; m < cnt; ++m) {
        unsigned long long pk = sbuf[m*TS + tid];
        float cd = __uint_as_float((unsigned)(pk >> 32));
        int ci = (int)(unsigned)pk;
        if (cd < bd[KK-1]) {
            #pragma unroll
            for (int s = 0; s < KK; ++s) {
                bool sw = cd < bd[s];
                float td = sw ? bd[s] : cd;
                int   ti = sw ? bi[s] : ci;
                if (sw) { bd[s] = cd; bi[s] = ci; }
                cd = td; ci = ti;
            }
        }
    }
    if (valid) {
        int off = (blockIdx.y * NN + q) * KK;
        #pragma unroll
        for (int s = 0; s < KK; ++s) { g_pd[off + s] = bd[s]; g_pi[off + s] = bi[s]; }
    }
}

// Merge SPL sorted 16-lists per query via head-scan argmin.
// Lists ordered by candidate range; strict '<' (prefer lowest list on ties)
// preserves lower-index-first semantics.
template<bool EMB>
__global__ void knn_merge_kernel() {
    int q = blockIdx.x * blockDim.x + threadIdx.x;
    if (q >= NN) return;
    int* out = EMB ? g_knn_e : g_knn_p;
    float hd[SPL];
    int   hp[SPL];
    #pragma unroll
    for (int l = 0; l < SPL; ++l) {
        hd[l] = g_pd[(l*NN + q) * KK];
        hp[l] = 0;
    }
    for (int s = 0; s < KK; ++s) {
        int best = 0; float bv = hd[0];
        #pragma unroll
        for (int l = 1; l < SPL; ++l) {
            if (hd[l] < bv) { bv = hd[l]; best = l; }
        }
        out[q*KK + s] = g_pi[(best*NN + q) * KK + hp[best]];
        hp[best]++;
        hd[best] = (hp[best] < KK) ? g_pd[(best*NN + q) * KK + hp[best]] : F_INF;
    }
}

// ---------------- 5. edge outputs ----------------
// out layout (float32, concatenated reference tuple):
//  [0,NK) p | [NK,2NK) p | [2NK,3NK) dst | [3NK,4NK) emb src | [4NK,5NK) dst
//  [5NK,6NK) emb src | [6NK,7NK) pos src | [7NK,8NK) dst | [8NK,9NK) dst
__global__ void edge_kernel(const float* __restrict__ t, float* __restrict__ out) {
    int e = blockIdx.x * blockDim.x + threadIdx.x;
    if (e >= NK) return;
    int dst = e >> 4;          // K = 16
    int src = g_knn_e[e];
    const float* a = g_embn + src * DD;
    const float* b = g_embn + dst * DD;
    float s = 0.f;
    #pragma unroll
    for (int d = 0; d < DD; ++d) {
        float df = a[d] - b[d];
        s = fmaf(df, df, s);
    }
    float p = expf(-t[0] * sqrtf(s));
    float fdst = (float)dst;
    out[e]          = p;
    out[NK   + e]   = p;
    out[2*NK + e]   = fdst;
    out[3*NK + e]   = (float)src;
    out[4*NK + e]   = fdst;
    out[5*NK + e]   = (float)src;
    out[6*NK + e]   = (float)g_knn_p[e];
    out[7*NK + e]   = fdst;
    out[8*NK + e]   = fdst;
}

// ---------------- launch ----------------
extern "C" void kernel_launch(void* const* d_in, const int* in_sizes, int n_in,
                              void* d_out, int out_size) {
    const float* x     = (const float*)d_in[0];
    const float* pos   = (const float*)d_in[1];
    const float* noise = (const float*)d_in[2];
    const float* W     = (const float*)d_in[3];
    const float* b     = (const float*)d_in[4];
    const float* gamma = (const float*)d_in[5];
    const float* beta  = (const float*)d_in[6];
    const float* t     = (const float*)d_in[7];
    float* out = (float*)d_out;

    const int TB = 128;
    int nb = (NN + TB - 1) / TB;      // 79

    mlp_kernel<<<nb, TB>>>(x, W, b);
    bn_stats_kernel<<<DD, 256>>>();
    bn_apply_kernel<<<nb, TB>>>(noise, gamma, beta, pos);

    dim3 kg(NBQ, SPL);
    knn_kernel<DD, DD, true><<<kg, TS>>>(nullptr);
    knn_merge_kernel<true><<<nb, TB>>>();
    knn_kernel<3, 4, false><<<kg, TS>>>(pos);
    knn_merge_kernel<false><<<nb, TB>>>();

    edge_kernel<<<(NK + 255) / 256, 256>>>(t, out);
}